// round 4
// baseline (speedup 1.0000x reference)
#include <cuda_runtime.h>

#define V      10
#define L      45          // V*(V-1)/2
#define NCOEF  14
#define RPB    128         // rows per block == threads per block
#define TPB    128
#define XPAD   11          // padded row stride for s_x
#define PSTR   16          // padded coeff stride for transposed params
#define LSTR   46          // padded row stride for s_lam

// M element map: ij -> lam index (>=0), -1 -> 0.0f, -2 -> 1.0f (diagonal)
__constant__ signed char c_map[V * V] = {
    -2,-1,-1,-1,-1,-1,-1,-1,-1,-1,
     0,-2,-1,-1,-1,-1,-1,-1,-1,-1,
     1, 2,-2,-1,-1,-1,-1,-1,-1,-1,
     3, 4, 5,-2,-1,-1,-1,-1,-1,-1,
     6, 7, 8, 9,-2,-1,-1,-1,-1,-1,
    10,11,12,13,14,-2,-1,-1,-1,-1,
    15,16,17,18,19,20,-2,-1,-1,-1,
    21,22,23,24,25,26,27,-2,-1,-1,
    28,29,30,31,32,33,34,35,-2,-1,
    36,37,38,39,40,41,42,43,44,-2
};

__device__ __forceinline__ float warp_sum(float v) {
#pragma unroll
    for (int o = 16; o > 0; o >>= 1) v += __shfl_down_sync(0xffffffffu, v, o);
    return v;
}

__global__ __launch_bounds__(TPB, 6)
void decor_kernel(const float* __restrict__ x,
                  const float* __restrict__ log_d,
                  const float* __restrict__ params,
                  float* __restrict__ out_all,
                  int n_rows)
{
    const int t = threadIdx.x;
    const int nblocks_main = (int)gridDim.x - 1;

    // ---------------- penalty block (last block): params-only ridge scalars ----------------
    if ((int)blockIdx.x == nblocks_main) {
        __shared__ float sp[NCOEF * L];
        __shared__ float red[3][TPB / 32];
        for (int i = t; i < NCOEF * L; i += TPB) sp[i] = params[i];
        __syncthreads();
        float par = 0.f, fir = 0.f, sec = 0.f;
        for (int i = t; i < NCOEF * L; i += TPB) { float v = sp[i]; par += v * v; }
        for (int i = t; i < (NCOEF - 1) * L; i += TPB) { float d = sp[i + L] - sp[i]; fir += d * d; }
        for (int i = t; i < (NCOEF - 2) * L; i += TPB) {
            float d = sp[i + 2 * L] - 2.f * sp[i + L] + sp[i];
            sec += d * d;
        }
        par = warp_sum(par); fir = warp_sum(fir); sec = warp_sum(sec);
        int lane = t & 31, w = t >> 5;
        if (lane == 0) { red[0][w] = sec; red[1][w] = fir; red[2][w] = par; }
        __syncthreads();
        if (w == 0) {
            float s = (lane < TPB / 32) ? red[0][lane] : 0.f;
            float f = (lane < TPB / 32) ? red[1][lane] : 0.f;
            float p = (lane < TPB / 32) ? red[2][lane] : 0.f;
            s = warp_sum(s); f = warp_sum(f); p = warp_sum(p);
            if (lane == 0) {
                float* tail = out_all + (size_t)n_rows * (V + V * V + V);
                tail[0] = s; tail[1] = f; tail[2] = p;
            }
        }
        return;
    }

    // ---------------- main blocks: one thread per row, coalesced writers ----------------
    __shared__ float s_p[L * PSTR];        // transposed params: s_p[l*16 + k] = params[k*L + l]
    __shared__ float s_x[RPB * XPAD];      // padded x tile
    __shared__ float s_lam[RPB * LSTR];    // per-row lambdas
    __shared__ float s_o[RPB * V];         // per-row outputs

    const int base = (int)blockIdx.x * RPB;
    const int nr = min(RPB, n_rows - base);

    for (int i = t; i < NCOEF * L; i += TPB) {
        int k = i / L, l = i - k * L;
        s_p[l * PSTR + k] = params[i];
    }
    for (int i = t; i < nr * V; i += TPB) {
        int r = i / V, c = i - r * V;
        s_x[r * XPAD + c] = x[(size_t)base * V + i];
    }
    __syncthreads();

    if (t < nr) {
        float xr[V];
#pragma unroll
        for (int c = 0; c < V; c++) xr[c] = s_x[t * XPAD + c];

        // 9 basis evaluations, 45 lambdas (uniform cubic B-spline closed form)
        const float INV_D = 11.0f / 10.0f;
        const float k6 = 1.0f / 6.0f;
        float lam[L];
#pragma unroll
        for (int j = 0; j < V - 1; j++) {
            float xc = fminf(fmaxf(xr[j], -5.0f), 5.0f);
            float tt = (xc + 5.0f) * INV_D;
            float fj = fminf(floorf(tt), 10.0f);
            float u  = tt - fj;
            int   jj = (int)fj;
            float um = 1.0f - u;
            float u2 = u * u, u3 = u2 * u;
            float w0 = um * um * um * k6;
            float w1 = (3.0f * u3 - 6.0f * u2 + 4.0f) * k6;
            float w2 = (-3.0f * u3 + 3.0f * u2 + 3.0f * u + 1.0f) * k6;
            float w3 = u3 * k6;
#pragma unroll
            for (int i = j + 1; i < V; i++) {
                const int l = (i * (i - 1)) / 2 + j;
                const float* p = s_p + l * PSTR + jj;
                lam[l] = w0 * p[0] + w1 * p[1] + w2 * p[2] + w3 * p[3];
            }
        }
#pragma unroll
        for (int l = 0; l < L; l++) s_lam[t * LSTR + l] = lam[l];

        // out[n,i] = x_i + sum_{j<i} lam_{ij} x_j  -> SMEM
#pragma unroll
        for (int i = 0; i < V; i++) {
            float acc = xr[i];
#pragma unroll
            for (int j = 0; j < i; j++) acc += lam[(i * (i - 1)) / 2 + j] * xr[j];
            s_o[t * V + i] = acc;
        }
    }
    __syncthreads();

    // ---- coalesced M writer: consecutive threads -> consecutive float4 ----
    {
        float4* Mb = (float4*)(out_all + (size_t)n_rows * V + (size_t)base * (V * V));
        const int nq = nr * 25;                 // 25 float4 per row (100 floats)
        for (int q = t; q < nq; q += TPB) {
            int r = q / 25, qq = q - r * 25;
            int ij0 = qq * 4;
            const float* lr = s_lam + r * LSTR;
            float4 v;
            float* vv = (float*)&v;
#pragma unroll
            for (int s = 0; s < 4; s++) {
                int m = c_map[ij0 + s];
                vv[s] = (m >= 0) ? lr[m] : ((m == -2) ? 1.0f : 0.0f);
            }
            Mb[q] = v;
        }
    }

    // ---- coalesced out writer: float2 granularity ----
    {
        float2* Ob = (float2*)(out_all + (size_t)base * V);
        const int nq = nr * 5;                  // 5 float2 per row
        for (int q = t; q < nq; q += TPB) {
            int r = q / 5, c = (q - r * 5) * 2;
            Ob[q] = make_float2(s_o[r * V + c], s_o[r * V + c + 1]);
        }
    }

    // ---- log_d passthrough (coalesced float4) ----
    {
        float* ldo = out_all + (size_t)n_rows * (V + V * V) + (size_t)base * V;
        const float* ldi = log_d + (size_t)base * V;
        int nfl = nr * V;
        if ((nfl & 3) == 0) {
            const float4* s4 = (const float4*)ldi;
            float4* d4 = (float4*)ldo;
            for (int q = t; q < nfl / 4; q += TPB) d4[q] = s4[q];
        } else {
            for (int q = t; q < nfl; q += TPB) ldo[q] = ldi[q];
        }
    }
}

extern "C" void kernel_launch(void* const* d_in, const int* in_sizes, int n_in,
                              void* d_out, int out_size)
{
    const float* x      = (const float*)d_in[0];
    const float* log_d  = (const float*)d_in[1];
    const float* params = (const float*)d_in[2];
    float* out_all = (float*)d_out;

    int n_rows = in_sizes[0] / V;
    int main_blocks = (n_rows + RPB - 1) / RPB;
    decor_kernel<<<main_blocks + 1, TPB>>>(x, log_d, params, out_all, n_rows);
}

// round 5
// speedup vs baseline: 3.1189x; 3.1189x over previous
#include <cuda_runtime.h>

#define V      10
#define L      45          // V*(V-1)/2
#define NCOEF  14
#define RPB    128         // rows per block == threads per block
#define TPB    128
#define MTILE  64          // rows staged per M phase
#define XPAD   11          // padded row stride for s_x
#define PSTR   16          // padded coeff stride for transposed params

__device__ __forceinline__ float warp_sum(float v) {
#pragma unroll
    for (int o = 16; o > 0; o >>= 1) v += __shfl_down_sync(0xffffffffu, v, o);
    return v;
}

__global__ __launch_bounds__(TPB, 6)
void decor_kernel(const float* __restrict__ x,
                  const float* __restrict__ log_d,
                  const float* __restrict__ params,
                  float* __restrict__ out_all,
                  int n_rows)
{
    const int t = threadIdx.x;
    const int nblocks_main = (int)gridDim.x - 1;

    // ---------------- penalty block (last block): params-only ridge scalars ----------------
    if ((int)blockIdx.x == nblocks_main) {
        __shared__ float sp[NCOEF * L];
        __shared__ float red[3][TPB / 32];
        for (int i = t; i < NCOEF * L; i += TPB) sp[i] = params[i];
        __syncthreads();
        float par = 0.f, fir = 0.f, sec = 0.f;
        for (int i = t; i < NCOEF * L; i += TPB) { float v = sp[i]; par += v * v; }
        for (int i = t; i < (NCOEF - 1) * L; i += TPB) { float d = sp[i + L] - sp[i]; fir += d * d; }
        for (int i = t; i < (NCOEF - 2) * L; i += TPB) {
            float d = sp[i + 2 * L] - 2.f * sp[i + L] + sp[i];
            sec += d * d;
        }
        par = warp_sum(par); fir = warp_sum(fir); sec = warp_sum(sec);
        int lane = t & 31, w = t >> 5;
        if (lane == 0) { red[0][w] = sec; red[1][w] = fir; red[2][w] = par; }
        __syncthreads();
        if (w == 0) {
            float s = (lane < TPB / 32) ? red[0][lane] : 0.f;
            float f = (lane < TPB / 32) ? red[1][lane] : 0.f;
            float p = (lane < TPB / 32) ? red[2][lane] : 0.f;
            s = warp_sum(s); f = warp_sum(f); p = warp_sum(p);
            if (lane == 0) {
                float* tail = out_all + (size_t)n_rows * (V + V * V + V);
                tail[0] = s; tail[1] = f; tail[2] = p;
            }
        }
        return;
    }

    // ---------------- main blocks: one thread per row ----------------
    __shared__ float  s_p[L * PSTR];          // transposed params: s_p[l*16+k] = params[k*L+l]
    __shared__ float  s_x[RPB * XPAD];        // padded x tile
    __shared__ float2 s_M2[MTILE][51];        // staged M rows (50 float2 used, pad to 51)

    const int base = (int)blockIdx.x * RPB;
    const int nr = min(RPB, n_rows - base);

    for (int i = t; i < NCOEF * L; i += TPB) {
        int k = i / L, l = i - k * L;
        s_p[l * PSTR + k] = params[i];
    }
    for (int i = t; i < nr * V; i += TPB) {
        int r = i / V, c = i - r * V;
        s_x[r * XPAD + c] = x[(size_t)base * V + i];
    }
    __syncthreads();

    // -------- per-thread compute: 9 basis evals -> 45 lambdas -> out row --------
    float lam[L];
    float xr[V];
    if (t < nr) {
#pragma unroll
        for (int c = 0; c < V; c++) xr[c] = s_x[t * XPAD + c];

        const float INV_D = 11.0f / 10.0f;   // knot spacing d = 10/11
        const float k6 = 1.0f / 6.0f;
#pragma unroll
        for (int j = 0; j < V - 1; j++) {
            float xc = fminf(fmaxf(xr[j], -5.0f), 5.0f);
            float tt = (xc + 5.0f) * INV_D;
            float fj = fminf(floorf(tt), 10.0f);
            float u  = tt - fj;
            int   jj = (int)fj;
            float um = 1.0f - u;
            float u2 = u * u, u3 = u2 * u;
            float w0 = um * um * um * k6;
            float w1 = (3.0f * u3 - 6.0f * u2 + 4.0f) * k6;
            float w2 = (-3.0f * u3 + 3.0f * u2 + 3.0f * u + 1.0f) * k6;
            float w3 = u3 * k6;
#pragma unroll
            for (int i = j + 1; i < V; i++) {
                const int l = (i * (i - 1)) / 2 + j;
                const float* p = s_p + l * PSTR + jj;   // conflict-free (PSTR=16, jj in [0,10])
                lam[l] = w0 * p[0] + w1 * p[1] + w2 * p[2] + w3 * p[3];
            }
        }

        // out[n,i] = x_i + sum_{j<i} lam_{ij} x_j  -> direct global (5x float2, small)
        float o[V];
#pragma unroll
        for (int i = 0; i < V; i++) {
            float acc = xr[i];
#pragma unroll
            for (int j = 0; j < i; j++) acc += lam[(i * (i - 1)) / 2 + j] * xr[j];
            o[i] = acc;
        }
        float2* orow = (float2*)(out_all + (size_t)(base + t) * V);
#pragma unroll
        for (int q = 0; q < V / 2; q++) orow[q] = make_float2(o[2 * q], o[2 * q + 1]);
    }

    // -------- M: two staged tiles of 64 rows, SMEM -> coalesced GMEM --------
    float2* Mb2 = (float2*)(out_all + (size_t)n_rows * V);
#pragma unroll
    for (int ph = 0; ph < RPB / MTILE; ph++) {
        const int r0 = ph * MTILE;
        const int cnt = min(MTILE, nr - r0);
        if (cnt <= 0) { __syncthreads(); __syncthreads(); continue; }

        __syncthreads();   // s_M2 free from previous phase
        if (t >= r0 && t < r0 + cnt) {
            float2* mrow = s_M2[t - r0];
            // fully unrolled: i,j,l all compile-time; no maps, no dynamic indexing
#pragma unroll
            for (int e2 = 0; e2 < 50; e2++) {
                const int e0 = 2 * e2, e1 = 2 * e2 + 1;
                const int i0 = e0 / V, j0 = e0 - i0 * V;
                const int i1 = e1 / V, j1 = e1 - i1 * V;
                float v0 = (i0 == j0) ? 1.0f : ((i0 > j0) ? lam[(i0 * (i0 - 1)) / 2 + j0] : 0.0f);
                float v1 = (i1 == j1) ? 1.0f : ((i1 > j1) ? lam[(i1 * (i1 - 1)) / 2 + j1] : 0.0f);
                mrow[e2] = make_float2(v0, v1);
            }
        }
        __syncthreads();

        // coalesced copy: cnt*50 float2, consecutive threads -> consecutive addresses
        const int nq = cnt * 50;
        for (int g = t; g < nq; g += TPB) {
            int r = g / 50, c = g - r * 50;
            Mb2[(size_t)(base + r0 + r) * 50 + c] = s_M2[r][c];
        }
    }

    // -------- log_d passthrough (coalesced float4) --------
    {
        float* ldo = out_all + (size_t)n_rows * (V + V * V) + (size_t)base * V;
        const float* ldi = log_d + (size_t)base * V;
        int nfl = nr * V;
        if ((nfl & 3) == 0) {
            const float4* s4 = (const float4*)ldi;
            float4* d4 = (float4*)ldo;
            for (int q = t; q < nfl / 4; q += TPB) d4[q] = s4[q];
        } else {
            for (int q = t; q < nfl; q += TPB) ldo[q] = ldi[q];
        }
    }
}

extern "C" void kernel_launch(void* const* d_in, const int* in_sizes, int n_in,
                              void* d_out, int out_size)
{
    const float* x      = (const float*)d_in[0];
    const float* log_d  = (const float*)d_in[1];
    const float* params = (const float*)d_in[2];
    float* out_all = (float*)d_out;

    int n_rows = in_sizes[0] / V;
    int main_blocks = (n_rows + RPB - 1) / RPB;
    decor_kernel<<<main_blocks + 1, TPB>>>(x, log_d, params, out_all, n_rows);
}